// round 6
// baseline (speedup 1.0000x reference)
#include <cuda_runtime.h>
#include <cuda_bf16.h>
#include <math.h>

#define BGRAPH 64
#define NNODE  256
#define FIN    256
#define OUTF   256
#define DEP    64
#define HID    256
#define G3     768
#define E_EDGES 262144
#define NN_TOT  16384

// ---------------- device scratch (accessed ONLY via symbol inside kernels) ----------------
__device__ __align__(16) float g_deg [NN_TOT];
__device__ __align__(16) float g_dinv[NN_TOT];
__device__ __align__(16) float g_beones[OUTF];
__device__ __align__(16) float g_Ax  [NN_TOT*OUTF];
__device__ __align__(16) float g_agg [NN_TOT*OUTF];
__device__ __align__(16) float g_seqA[NN_TOT*OUTF];
__device__ __align__(16) float g_seqB[NN_TOT*OUTF];
__device__ __align__(16) float g_xp  [NN_TOT*G3];
__device__ __align__(16) float g_wt  [3][64*G3*4];   // [layer][(c*768+t)*4+j] = w_hh[t][4c+j]
__device__ __align__(16) float g_ht  [3*BGRAPH*HID];

__device__ __forceinline__ float sigf(float x){ return 1.0f/(1.0f+expf(-x)); }

// ---------------- degree ----------------
__global__ void k_deg_init(){ g_deg[blockIdx.x*256+threadIdx.x] = 1.0f; }
__global__ void k_deg_count(const int* __restrict__ eidx){
    int e = blockIdx.x*256+threadIdx.x;
    atomicAdd(&g_deg[eidx[E_EDGES+e]], 1.0f);
}
__global__ void k_dinv(){
    int i = blockIdx.x*256+threadIdx.x;
    g_dinv[i] = rsqrtf(g_deg[i]);
}
__global__ void k_beones(const float* __restrict__ WB){
    int j = threadIdx.x; float s = 0.f;
    for (int k=0;k<DEP;k++) s += WB[j*DEP+k];
    g_beones[j] = s;
}

// ---------------- SGEMM: C[m][n] = sum_k A[m][k]*B[n][k] (+bias[n]), K=256 ----------------
// Aext != nullptr -> external input; else asel: 0=g_seqA, 1=g_seqB.
// csel: 0 -> g_Ax, 1 -> g_xp.
__global__ void __launch_bounds__(256) k_gemm(const float* __restrict__ Aext, int asel,
                                              const float* __restrict__ B,
                                              const float* __restrict__ bias,
                                              int csel, int N){
    const float* A = Aext ? Aext : (asel == 0 ? (const float*)g_seqA : (const float*)g_seqB);
    float* C = (csel == 0) ? g_Ax : g_xp;
    const int K = 256;
    __shared__ float As[16][64];
    __shared__ float Bs[16][64];
    int bm = blockIdx.y*64, bn = blockIdx.x*64;
    int t = threadIdx.x;
    int tx = t & 15, ty = t >> 4;
    int lr = t >> 2, lk = (t & 3)*4;

    float acc[4][4];
#pragma unroll
    for (int i=0;i<4;i++)
#pragma unroll
        for (int j=0;j<4;j++) acc[i][j]=0.f;

    for (int k0=0;k0<K;k0+=16){
        float4 a = *(const float4*)&A[(size_t)(bm+lr)*K + k0 + lk];
        float4 b = *(const float4*)&B[(size_t)(bn+lr)*K + k0 + lk];
        __syncthreads();
        As[lk+0][lr]=a.x; As[lk+1][lr]=a.y; As[lk+2][lr]=a.z; As[lk+3][lr]=a.w;
        Bs[lk+0][lr]=b.x; Bs[lk+1][lr]=b.y; Bs[lk+2][lr]=b.z; Bs[lk+3][lr]=b.w;
        __syncthreads();
#pragma unroll
        for (int kk=0;kk<16;kk++){
            float4 av = *(const float4*)&As[kk][ty*4];
            float4 bv = *(const float4*)&Bs[kk][tx*4];
            acc[0][0]+=av.x*bv.x; acc[0][1]+=av.x*bv.y; acc[0][2]+=av.x*bv.z; acc[0][3]+=av.x*bv.w;
            acc[1][0]+=av.y*bv.x; acc[1][1]+=av.y*bv.y; acc[1][2]+=av.y*bv.z; acc[1][3]+=av.y*bv.w;
            acc[2][0]+=av.z*bv.x; acc[2][1]+=av.z*bv.y; acc[2][2]+=av.z*bv.z; acc[2][3]+=av.z*bv.w;
            acc[3][0]+=av.w*bv.x; acc[3][1]+=av.w*bv.y; acc[3][2]+=av.w*bv.z; acc[3][3]+=av.w*bv.w;
        }
    }
    float4 bv4 = make_float4(0.f,0.f,0.f,0.f);
    if (bias) bv4 = *(const float4*)&bias[bn + tx*4];
#pragma unroll
    for (int i=0;i<4;i++){
        float4 o;
        o.x=acc[i][0]+bv4.x; o.y=acc[i][1]+bv4.y; o.z=acc[i][2]+bv4.z; o.w=acc[i][3]+bv4.w;
        *(float4*)&C[(size_t)(bm+ty*4+i)*N + bn + tx*4] = o;
    }
}

// ---------------- GCN self-loop init of agg ----------------
__global__ void k_self(){
    int idx = blockIdx.x*256+threadIdx.x;     // over 16384*256
    int i = idx >> 8, j = idx & 255;
    float dv = g_dinv[i];
    g_agg[idx] = dv*dv*tanhf(g_Ax[idx]*g_beones[j]);
}

// ---------------- GCN edge aggregation (global atomics) ----------------
__global__ void __launch_bounds__(256) k_edge(const float* __restrict__ eattr,
                                              const int*   __restrict__ eidx,
                                              const float* __restrict__ WB){
    extern __shared__ float sh[];
    float* WBt   = sh;              // [64][256] k-major
    float* ea_sh = WBt + 64*256;    // [8][64]
    float* snorm = ea_sh + 8*64;    // [8]
    int*   ssrc  = (int*)(snorm+8); // [8]
    int*   sdst  = ssrc + 8;        // [8]

    int t = threadIdx.x;
    for (int idx=t; idx<64*256; idx+=256){
        int j = idx & 255, k = idx >> 8;
        WBt[idx] = WB[j*DEP + k];       // WBt[k*256+j]
    }
    int w = t >> 5, lane = t & 31;
    int base = blockIdx.x*256;

    for (int b=0;b<32;b++){
        __syncthreads();
        int e0 = base + b*8;
        if (t < 8){
            int e = e0 + t;
            int s = eidx[e], d = eidx[E_EDGES+e];
            ssrc[t]=s; sdst[t]=d; snorm[t]=g_dinv[s]*g_dinv[d];
        }
        {
            int e = t >> 5, k2 = (t & 31)*2;
            *(float2*)&ea_sh[e*64+k2] = *(const float2*)&eattr[(size_t)(e0+e)*DEP + k2];
        }
        __syncthreads();

        int   src = ssrc[w], dst = sdst[w];
        float nr  = snorm[w];
        const float* ea = &ea_sh[w*64];
#pragma unroll
        for (int p=0;p<2;p++){
            int j = p*128 + lane*4;
            float4 acc = make_float4(0.f,0.f,0.f,0.f);
#pragma unroll 8
            for (int k=0;k<64;k++){
                float a = ea[k];
                float4 wv = *(const float4*)&WBt[k*256 + j];
                acc.x += a*wv.x; acc.y += a*wv.y; acc.z += a*wv.z; acc.w += a*wv.w;
            }
            float4 ax = *(const float4*)&g_Ax[(size_t)src*256 + j];
            float* ag = &g_agg[(size_t)dst*256 + j];
            atomicAdd(&ag[0], nr*tanhf(ax.x*acc.x));
            atomicAdd(&ag[1], nr*tanhf(ax.y*acc.y));
            atomicAdd(&ag[2], nr*tanhf(ax.z*acc.z));
            atomicAdd(&ag[3], nr*tanhf(ax.w*acc.w));
        }
    }
}

// ---------------- node = tanh(agg/deg + bias) -> g_seqA ----------------
__global__ void k_node(const float* __restrict__ gbias){
    int idx = blockIdx.x*256+threadIdx.x;
    int i = idx >> 8, j = idx & 255;
    g_seqA[idx] = tanhf(g_agg[idx]/g_deg[i] + gbias[j]);
}

// ---------------- transpose w_hh into k-chunked layout ----------------
__global__ void k_wt(const float* __restrict__ whh, int layer){
    int idx = blockIdx.x*256+threadIdx.x;   // over 768*256
    int t = idx >> 8, k = idx & 255;
    g_wt[layer][( (k>>2)*G3 + t)*4 + (k&3)] = whh[t*256 + k];
}

// ---------------- GRU recurrence: 1 CTA per graph, 768 threads ----------------
#define SC 16  // k-chunks resident in smem (covers k<64), 196608 B dynamic
__global__ void __launch_bounds__(768) k_gru(const float* __restrict__ bhh,
                                             int osel, int layer){
    extern __shared__ float swt[];                 // [SC*3072]
    __shared__ __align__(16) float h[HID];
    __shared__ float gh[G3];
    int g = blockIdx.x, t = threadIdx.x;

    float* seqout = osel ? g_seqB : g_seqA;
    const float* wl = g_wt[layer];
    for (int idx=t; idx<SC*G3; idx+=768)
        *(float4*)&swt[idx*4] = *(const float4*)&wl[idx*4];
    if (t < HID) h[t] = 0.f;
    float bb = bhh[t];
    const float* xpr = &g_xp[(size_t)g*256*G3];
    __syncthreads();

    for (int s=0;s<256;s++){
        float acc = bb;
#pragma unroll
        for (int c=0;c<SC;c++){
            float4 wv = *(const float4*)&swt[(c*G3+t)*4];
            float4 hv = *(const float4*)&h[c*4];
            acc += wv.x*hv.x + wv.y*hv.y + wv.z*hv.z + wv.w*hv.w;
        }
#pragma unroll 8
        for (int c=SC;c<64;c++){
            float4 wv = *(const float4*)&wl[(c*G3+t)*4];
            float4 hv = *(const float4*)&h[c*4];
            acc += wv.x*hv.x + wv.y*hv.y + wv.z*hv.z + wv.w*hv.w;
        }
        gh[t] = acc;
        __syncthreads();
        if (t < HID){
            const float* xr = &xpr[(size_t)s*G3];
            float r = sigf(xr[t]       + gh[t]);
            float z = sigf(xr[256+t]   + gh[256+t]);
            float n = tanhf(xr[512+t] + r*gh[512+t]);
            float hn = (1.f-z)*n + z*h[t];
            h[t] = hn;
            seqout[(size_t)(g*256+s)*HID + t] = hn;
        }
        __syncthreads();
    }
    if (t < HID) g_ht[layer*NN_TOT + g*HID + t] = h[t];
}

// ---------------- pooling + linear + softmax ----------------
__global__ void __launch_bounds__(256) k_final(const float* __restrict__ linW,
                                               const float* __restrict__ linb,
                                               float* __restrict__ out){
    __shared__ float r0[256], r1[256];
    int g = blockIdx.x, j = threadIdx.x;
    float mx = -1e30f, sm = 0.f;
    const float* seq = &g_seqB[(size_t)g*256*HID];
    for (int s=0;s<256;s++){
        float v = seq[(size_t)s*HID + j];
        mx = fmaxf(mx, v); sm += v;
    }
    float avg = sm * (1.0f/256.0f);
    float h0 = g_ht[0*NN_TOT + g*HID + j];
    float h1 = g_ht[1*NN_TOT + g*HID + j];
    float h2 = g_ht[2*NN_TOT + g*HID + j];
    float p0 = h0*linW[j] + h1*linW[256+j] + h2*linW[512+j] + mx*linW[768+j] + avg*linW[1024+j];
    float p1 = h0*linW[1280+j] + h1*linW[1536+j] + h2*linW[1792+j] + mx*linW[2048+j] + avg*linW[2304+j];
    r0[j] = p0; r1[j] = p1;
    __syncthreads();
    for (int stp=128; stp>0; stp>>=1){
        if (j < stp){ r0[j]+=r0[j+stp]; r1[j]+=r1[j+stp]; }
        __syncthreads();
    }
    if (j == 0){
        float l0 = r0[0] + linb[0], l1 = r1[0] + linb[1];
        float m = fmaxf(l0,l1);
        float e0 = expf(l0-m), e1 = expf(l1-m);
        float inv = 1.0f/(e0+e1);
        out[g*2+0] = e0*inv;
        out[g*2+1] = e1*inv;
    }
}

// ---------------- launch ----------------
extern "C" void kernel_launch(void* const* d_in, const int* in_sizes, int n_in,
                              void* d_out, int out_size){
    const float* x      = (const float*)d_in[0];
    const float* eattr  = (const float*)d_in[1];
    const int*   eidx   = (const int*)  d_in[2];
    const float* WA     = (const float*)d_in[3];
    const float* WB     = (const float*)d_in[4];
    const float* gbias  = (const float*)d_in[5];
    const float* wih[3] = {(const float*)d_in[6],  (const float*)d_in[10], (const float*)d_in[14]};
    const float* whh[3] = {(const float*)d_in[7],  (const float*)d_in[11], (const float*)d_in[15]};
    const float* bih[3] = {(const float*)d_in[8],  (const float*)d_in[12], (const float*)d_in[16]};
    const float* bhh[3] = {(const float*)d_in[9],  (const float*)d_in[13], (const float*)d_in[17]};
    const float* linW   = (const float*)d_in[18];
    const float* linb   = (const float*)d_in[19];
    float* out = (float*)d_out;

    size_t edge_smem = (64*256 + 8*64 + 8)*sizeof(float) + 16*sizeof(int) + 64;
    size_t gru_smem  = SC*G3*4*sizeof(float);
    cudaFuncSetAttribute(k_edge, cudaFuncAttributeMaxDynamicSharedMemorySize, (int)edge_smem);
    cudaFuncSetAttribute(k_gru,  cudaFuncAttributeMaxDynamicSharedMemorySize, (int)gru_smem);

    k_deg_init<<<NN_TOT/256, 256>>>();
    k_deg_count<<<E_EDGES/256, 256>>>(eidx);
    k_dinv<<<NN_TOT/256, 256>>>();
    k_beones<<<1, 256>>>(WB);
    // Ax = x @ WA^T  -> g_Ax (csel=0)
    k_gemm<<<dim3(OUTF/64, NN_TOT/64), 256>>>(x, 0, WA, nullptr, 0, OUTF);
    k_self<<<NN_TOT*OUTF/256, 256>>>();
    k_edge<<<1024, 256, edge_smem>>>(eattr, eidx, WB);
    k_node<<<NN_TOT*OUTF/256, 256>>>(gbias);     // -> g_seqA
    for (int l=0;l<3;l++) k_wt<<<G3*256/256, 256>>>(whh[l], l);

    // layer l: input buffer (0=A,1=B), output buffer
    const int insel[3]  = {0, 1, 0};
    const int outsel[3] = {1, 0, 1};
    for (int l=0;l<3;l++){
        // xp = seq_in @ w_ih^T + b_ih -> g_xp (csel=1)
        k_gemm<<<dim3(G3/64, NN_TOT/64), 256>>>(nullptr, insel[l], wih[l], bih[l], 1, G3);
        k_gru<<<BGRAPH, 768, gru_smem>>>(bhh[l], outsel[l], l);
    }
    // layer-2 output lives in g_seqB; k_final reads it directly
    k_final<<<BGRAPH, 256>>>(linW, linb, out);
}

// round 8
// speedup vs baseline: 1.2132x; 1.2132x over previous
#include <cuda_runtime.h>
#include <cuda_bf16.h>
#include <cstdint>
#include <math.h>

#define BGRAPH 64
#define NNODE  256
#define FIN    256
#define OUTF   256
#define DEP    64
#define HID    256
#define G3     768
#define E_EDGES 262144
#define NN_TOT  16384

// ---------------- device scratch (accessed ONLY via symbol inside kernels) ----------------
__device__ __align__(16) float g_deg [NN_TOT];
__device__ __align__(16) float g_dinv[NN_TOT];
__device__ __align__(16) float g_beones[OUTF];
__device__ __align__(16) float g_Ax  [NN_TOT*OUTF];
__device__ __align__(16) float g_agg [NN_TOT*OUTF];
__device__ __align__(16) float g_seqA[NN_TOT*OUTF];
__device__ __align__(16) float g_seqB[NN_TOT*OUTF];
__device__ __align__(16) float g_xp  [NN_TOT*G3];
__device__ __align__(16) float g_wt  [3][64*G3*4];   // [layer][(c*768+t)*4+j] = w_hh[t][4c+j]
__device__ __align__(16) float g_ht  [3*BGRAPH*HID];

__device__ __forceinline__ float sigf(float x){ return 1.0f/(1.0f+expf(-x)); }

// ---------------- degree ----------------
__global__ void k_deg_init(){ g_deg[blockIdx.x*256+threadIdx.x] = 1.0f; }
__global__ void k_deg_count(const int* __restrict__ eidx){
    int e = blockIdx.x*256+threadIdx.x;
    atomicAdd(&g_deg[eidx[E_EDGES+e]], 1.0f);
}
__global__ void k_dinv(){
    int i = blockIdx.x*256+threadIdx.x;
    g_dinv[i] = rsqrtf(g_deg[i]);
}
__global__ void k_beones(const float* __restrict__ WB){
    int j = threadIdx.x; float s = 0.f;
    for (int k=0;k<DEP;k++) s += WB[j*DEP+k];
    g_beones[j] = s;
}

// ---------------- SGEMM: C[m][n] = sum_k A[m][k]*B[n][k] (+bias[n]), K=256 ----------------
__global__ void __launch_bounds__(256) k_gemm(const float* __restrict__ Aext, int asel,
                                              const float* __restrict__ B,
                                              const float* __restrict__ bias,
                                              int csel, int N){
    const float* A = Aext ? Aext : (asel == 0 ? (const float*)g_seqA : (const float*)g_seqB);
    float* C = (csel == 0) ? g_Ax : g_xp;
    const int K = 256;
    __shared__ float As[16][64];
    __shared__ float Bs[16][64];
    int bm = blockIdx.y*64, bn = blockIdx.x*64;
    int t = threadIdx.x;
    int tx = t & 15, ty = t >> 4;
    int lr = t >> 2, lk = (t & 3)*4;

    float acc[4][4];
#pragma unroll
    for (int i=0;i<4;i++)
#pragma unroll
        for (int j=0;j<4;j++) acc[i][j]=0.f;

    for (int k0=0;k0<K;k0+=16){
        float4 a = *(const float4*)&A[(size_t)(bm+lr)*K + k0 + lk];
        float4 b = *(const float4*)&B[(size_t)(bn+lr)*K + k0 + lk];
        __syncthreads();
        As[lk+0][lr]=a.x; As[lk+1][lr]=a.y; As[lk+2][lr]=a.z; As[lk+3][lr]=a.w;
        Bs[lk+0][lr]=b.x; Bs[lk+1][lr]=b.y; Bs[lk+2][lr]=b.z; Bs[lk+3][lr]=b.w;
        __syncthreads();
#pragma unroll
        for (int kk=0;kk<16;kk++){
            float4 av = *(const float4*)&As[kk][ty*4];
            float4 bv = *(const float4*)&Bs[kk][tx*4];
            acc[0][0]+=av.x*bv.x; acc[0][1]+=av.x*bv.y; acc[0][2]+=av.x*bv.z; acc[0][3]+=av.x*bv.w;
            acc[1][0]+=av.y*bv.x; acc[1][1]+=av.y*bv.y; acc[1][2]+=av.y*bv.z; acc[1][3]+=av.y*bv.w;
            acc[2][0]+=av.z*bv.x; acc[2][1]+=av.z*bv.y; acc[2][2]+=av.z*bv.z; acc[2][3]+=av.z*bv.w;
            acc[3][0]+=av.w*bv.x; acc[3][1]+=av.w*bv.y; acc[3][2]+=av.w*bv.z; acc[3][3]+=av.w*bv.w;
        }
    }
    float4 bv4 = make_float4(0.f,0.f,0.f,0.f);
    if (bias) bv4 = *(const float4*)&bias[bn + tx*4];
#pragma unroll
    for (int i=0;i<4;i++){
        float4 o;
        o.x=acc[i][0]+bv4.x; o.y=acc[i][1]+bv4.y; o.z=acc[i][2]+bv4.z; o.w=acc[i][3]+bv4.w;
        *(float4*)&C[(size_t)(bm+ty*4+i)*N + bn + tx*4] = o;
    }
}

// ---------------- GCN self-loop init of agg ----------------
__global__ void k_self(){
    int idx = blockIdx.x*256+threadIdx.x;
    int i = idx >> 8, j = idx & 255;
    float dv = g_dinv[i];
    g_agg[idx] = dv*dv*tanhf(g_Ax[idx]*g_beones[j]);
}

// ---------------- GCN edge aggregation (global atomics) ----------------
__global__ void __launch_bounds__(256) k_edge(const float* __restrict__ eattr,
                                              const int*   __restrict__ eidx,
                                              const float* __restrict__ WB){
    extern __shared__ float sh[];
    float* WBt   = sh;              // [64][256] k-major
    float* ea_sh = WBt + 64*256;    // [8][64]
    float* snorm = ea_sh + 8*64;    // [8]
    int*   ssrc  = (int*)(snorm+8); // [8]
    int*   sdst  = ssrc + 8;        // [8]

    int t = threadIdx.x;
    for (int idx=t; idx<64*256; idx+=256){
        int j = idx & 255, k = idx >> 8;
        WBt[idx] = WB[j*DEP + k];
    }
    int w = t >> 5, lane = t & 31;
    int base = blockIdx.x*256;

    for (int b=0;b<32;b++){
        __syncthreads();
        int e0 = base + b*8;
        if (t < 8){
            int e = e0 + t;
            int s = eidx[e], d = eidx[E_EDGES+e];
            ssrc[t]=s; sdst[t]=d; snorm[t]=g_dinv[s]*g_dinv[d];
        }
        {
            int e = t >> 5, k2 = (t & 31)*2;
            *(float2*)&ea_sh[e*64+k2] = *(const float2*)&eattr[(size_t)(e0+e)*DEP + k2];
        }
        __syncthreads();

        int   src = ssrc[w], dst = sdst[w];
        float nr  = snorm[w];
        const float* ea = &ea_sh[w*64];
#pragma unroll
        for (int p=0;p<2;p++){
            int j = p*128 + lane*4;
            float4 acc = make_float4(0.f,0.f,0.f,0.f);
#pragma unroll 8
            for (int k=0;k<64;k++){
                float a = ea[k];
                float4 wv = *(const float4*)&WBt[k*256 + j];
                acc.x += a*wv.x; acc.y += a*wv.y; acc.z += a*wv.z; acc.w += a*wv.w;
            }
            float4 ax = *(const float4*)&g_Ax[(size_t)src*256 + j];
            float* ag = &g_agg[(size_t)dst*256 + j];
            atomicAdd(&ag[0], nr*tanhf(ax.x*acc.x));
            atomicAdd(&ag[1], nr*tanhf(ax.y*acc.y));
            atomicAdd(&ag[2], nr*tanhf(ax.z*acc.z));
            atomicAdd(&ag[3], nr*tanhf(ax.w*acc.w));
        }
    }
}

// ---------------- node = tanh(agg/deg + bias) -> g_seqA ----------------
__global__ void k_node(const float* __restrict__ gbias){
    int idx = blockIdx.x*256+threadIdx.x;
    int i = idx >> 8, j = idx & 255;
    g_seqA[idx] = tanhf(g_agg[idx]/g_deg[i] + gbias[j]);
}

// ---------------- transpose w_hh into k-chunked layout ----------------
__global__ void k_wt(const float* __restrict__ whh, int layer){
    int idx = blockIdx.x*256+threadIdx.x;   // over 768*256
    int t = idx >> 8, k = idx & 255;
    g_wt[layer][( (k>>2)*G3 + t)*4 + (k&3)] = whh[t*256 + k];
}

// ---------------- GRU recurrence v2: cluster of 2 CTAs per graph ----------------
// 128 CTAs (64 clusters x 2). CTA rank r owns gh rows {band*256 + r*128 + idx},
// band in {0(r-gate),1(z),2(n)}, idx in [0,128). Weights for k<128 smem-resident
// (192KB); k in [128,256) streamed via LDG. h double-buffered; halves exchanged
// via st.shared::cluster; one cluster barrier per step.
#define RC 32   // resident k-chunks (4 dims each) = k<128
__global__ void __launch_bounds__(384) __cluster_dims__(2,1,1)
k_gru(const float* __restrict__ bhh, int osel, int layer){
    extern __shared__ float sw[];                    // [RC*384*4] = 196608 B
    __shared__ __align__(16) float h[2][HID];
    __shared__ float gh[3][128];
    int bx = blockIdx.x;
    int g = bx >> 1, rank = bx & 1;
    int tid = threadIdx.x;
    int band = tid >> 7, idx = tid & 127;
    int row = band*256 + rank*128 + idx;             // global gh row
    int u = rank*128 + idx;                          // hidden unit (band 0 threads)
    float* seqout = osel ? g_seqB : g_seqA;
    const float* wl = g_wt[layer];

    // stage resident half: sw[(c*384 + tid)*4 + j] = wl[(c*768 + row)*4 + j]
#pragma unroll 4
    for (int c=0; c<RC; c++)
        *(float4*)&sw[(c*384 + tid)*4] = *(const float4*)&wl[(c*768 + row)*4];
    if (tid < HID) h[0][tid] = 0.f;
    float bb = bhh[row];
    const float* xpr = &g_xp[(size_t)g*256*G3];
    asm volatile("barrier.cluster.arrive.aligned;" ::: "memory");
    asm volatile("barrier.cluster.wait.aligned;"  ::: "memory");

    for (int s=0; s<256; s++){
        int rp = s & 1, wp = rp ^ 1;
        float x0=0.f, x1=0.f, x2=0.f;
        if (band == 0){                              // prefetch xr for this step
            const float* xr = &xpr[(size_t)s*G3];
            x0 = xr[u]; x1 = xr[256+u]; x2 = xr[512+u];
        }
        const float* hp = h[rp];
        float a0=0.f, a1=0.f, a2=0.f, a3=0.f;
#pragma unroll
        for (int c=0; c<RC; c+=4){
            float4 w0=*(const float4*)&sw[((c+0)*384+tid)*4];
            float4 w1=*(const float4*)&sw[((c+1)*384+tid)*4];
            float4 w2=*(const float4*)&sw[((c+2)*384+tid)*4];
            float4 w3=*(const float4*)&sw[((c+3)*384+tid)*4];
            float4 h0=*(const float4*)&hp[(c+0)*4];
            float4 h1=*(const float4*)&hp[(c+1)*4];
            float4 h2=*(const float4*)&hp[(c+2)*4];
            float4 h3=*(const float4*)&hp[(c+3)*4];
            a0 += w0.x*h0.x + w0.y*h0.y + w0.z*h0.z + w0.w*h0.w;
            a1 += w1.x*h1.x + w1.y*h1.y + w1.z*h1.z + w1.w*h1.w;
            a2 += w2.x*h2.x + w2.y*h2.y + w2.z*h2.z + w2.w*h2.w;
            a3 += w3.x*h3.x + w3.y*h3.y + w3.z*h3.z + w3.w*h3.w;
        }
#pragma unroll
        for (int c=RC; c<64; c+=4){
            float4 w0=*(const float4*)&wl[((c+0)*768+row)*4];
            float4 w1=*(const float4*)&wl[((c+1)*768+row)*4];
            float4 w2=*(const float4*)&wl[((c+2)*768+row)*4];
            float4 w3=*(const float4*)&wl[((c+3)*768+row)*4];
            float4 h0=*(const float4*)&hp[(c+0)*4];
            float4 h1=*(const float4*)&hp[(c+1)*4];
            float4 h2=*(const float4*)&hp[(c+2)*4];
            float4 h3=*(const float4*)&hp[(c+3)*4];
            a0 += w0.x*h0.x + w0.y*h0.y + w0.z*h0.z + w0.w*h0.w;
            a1 += w1.x*h1.x + w1.y*h1.y + w1.z*h1.z + w1.w*h1.w;
            a2 += w2.x*h2.x + w2.y*h2.y + w2.z*h2.z + w2.w*h2.w;
            a3 += w3.x*h3.x + w3.y*h3.y + w3.z*h3.z + w3.w*h3.w;
        }
        gh[band][idx] = a0 + a1 + a2 + a3 + bb;
        __syncthreads();
        if (band == 0){
            float r = sigf(x0 + gh[0][idx]);
            float z = sigf(x1 + gh[1][idx]);
            float n = tanhf(x2 + r*gh[2][idx]);
            float hn = (1.f - z)*n + z*hp[u];
            h[wp][u] = hn;
            uint32_t la = (uint32_t)__cvta_generic_to_shared(&h[wp][u]);
            uint32_t ra;
            asm("mapa.shared::cluster.u32 %0, %1, %2;" : "=r"(ra) : "r"(la), "r"(rank^1));
            asm volatile("st.shared::cluster.f32 [%0], %1;" :: "r"(ra), "f"(hn));
            seqout[(size_t)(g*256+s)*HID + u] = hn;
        }
        asm volatile("barrier.cluster.arrive.aligned;" ::: "memory");
        asm volatile("barrier.cluster.wait.aligned;"  ::: "memory");
    }
    if (band == 0) g_ht[layer*NN_TOT + g*HID + u] = h[0][u];  // step 255 wrote wp=0
}

// ---------------- pooling + linear + softmax ----------------
__global__ void __launch_bounds__(256) k_final(const float* __restrict__ linW,
                                               const float* __restrict__ linb,
                                               float* __restrict__ out){
    __shared__ float r0[256], r1[256];
    int g = blockIdx.x, j = threadIdx.x;
    float mx = -1e30f, sm = 0.f;
    const float* seq = &g_seqB[(size_t)g*256*HID];
    for (int s=0;s<256;s++){
        float v = seq[(size_t)s*HID + j];
        mx = fmaxf(mx, v); sm += v;
    }
    float avg = sm * (1.0f/256.0f);
    float h0 = g_ht[0*NN_TOT + g*HID + j];
    float h1 = g_ht[1*NN_TOT + g*HID + j];
    float h2 = g_ht[2*NN_TOT + g*HID + j];
    float p0 = h0*linW[j] + h1*linW[256+j] + h2*linW[512+j] + mx*linW[768+j] + avg*linW[1024+j];
    float p1 = h0*linW[1280+j] + h1*linW[1536+j] + h2*linW[1792+j] + mx*linW[2048+j] + avg*linW[2304+j];
    r0[j] = p0; r1[j] = p1;
    __syncthreads();
    for (int stp=128; stp>0; stp>>=1){
        if (j < stp){ r0[j]+=r0[j+stp]; r1[j]+=r1[j+stp]; }
        __syncthreads();
    }
    if (j == 0){
        float l0 = r0[0] + linb[0], l1 = r1[0] + linb[1];
        float m = fmaxf(l0,l1);
        float e0 = expf(l0-m), e1 = expf(l1-m);
        float inv = 1.0f/(e0+e1);
        out[g*2+0] = e0*inv;
        out[g*2+1] = e1*inv;
    }
}

// ---------------- launch ----------------
extern "C" void kernel_launch(void* const* d_in, const int* in_sizes, int n_in,
                              void* d_out, int out_size){
    const float* x      = (const float*)d_in[0];
    const float* eattr  = (const float*)d_in[1];
    const int*   eidx   = (const int*)  d_in[2];
    const float* WA     = (const float*)d_in[3];
    const float* WB     = (const float*)d_in[4];
    const float* gbias  = (const float*)d_in[5];
    const float* wih[3] = {(const float*)d_in[6],  (const float*)d_in[10], (const float*)d_in[14]};
    const float* whh[3] = {(const float*)d_in[7],  (const float*)d_in[11], (const float*)d_in[15]};
    const float* bih[3] = {(const float*)d_in[8],  (const float*)d_in[12], (const float*)d_in[16]};
    const float* bhh[3] = {(const float*)d_in[9],  (const float*)d_in[13], (const float*)d_in[17]};
    const float* linW   = (const float*)d_in[18];
    const float* linb   = (const float*)d_in[19];
    float* out = (float*)d_out;

    size_t edge_smem = (64*256 + 8*64 + 8)*sizeof(float) + 16*sizeof(int) + 64;
    size_t gru_smem  = (size_t)RC*384*4*sizeof(float);   // 196608 B
    cudaFuncSetAttribute(k_edge, cudaFuncAttributeMaxDynamicSharedMemorySize, (int)edge_smem);
    cudaFuncSetAttribute(k_gru,  cudaFuncAttributeMaxDynamicSharedMemorySize, (int)gru_smem);

    k_deg_init<<<NN_TOT/256, 256>>>();
    k_deg_count<<<E_EDGES/256, 256>>>(eidx);
    k_dinv<<<NN_TOT/256, 256>>>();
    k_beones<<<1, 256>>>(WB);
    k_gemm<<<dim3(OUTF/64, NN_TOT/64), 256>>>(x, 0, WA, nullptr, 0, OUTF);
    k_self<<<NN_TOT*OUTF/256, 256>>>();
    k_edge<<<1024, 256, edge_smem>>>(eattr, eidx, WB);
    k_node<<<NN_TOT*OUTF/256, 256>>>(gbias);
    for (int l=0;l<3;l++) k_wt<<<G3*256/256, 256>>>(whh[l], l);

    const int insel[3]  = {0, 1, 0};
    const int outsel[3] = {1, 0, 1};
    for (int l=0;l<3;l++){
        k_gemm<<<dim3(G3/64, NN_TOT/64), 256>>>(nullptr, insel[l], wih[l], bih[l], 1, G3);
        k_gru<<<2*BGRAPH, 384, gru_smem>>>(bhh[l], outsel[l], l);
    }
    k_final<<<BGRAPH, 256>>>(linW, linb, out);
}